// round 7
// baseline (speedup 1.0000x reference)
#include <cuda_runtime.h>
#include <cuda_bf16.h>
#include <cstdint>

typedef unsigned long long ull;

#define BROWS 8192
#define NOUT  512
#define NKDIM 512
#define NCODE 512
#define GROUPS 4096
#define WDIM   64

#define KA    1024          // stored A width: [Ah | Al]
#define KB    1024          // stored B width: [Bh | Bl]
#define GBM   128
#define GBN   128
#define GBK   32
#define KITERS 48           // 3 logical segments * 16 chunks
#define ASTR  40            // padded bf16 row stride (80B -> conflict-free ldmatrix)
#define NSTAGE 3
#define SMEM_ELEMS (NSTAGE * (GBM + GBN) * ASTR)

// ---------------- device scratch ----------------
__device__ __nv_bfloat16 g_A2[BROWS * KA];   // 16.8 MB
__device__ __nv_bfloat16 g_B2[NOUT * KB];    // 1.0 MB
__device__ int   g_idx[GROUPS];
__device__ float g_mind[GROUPS];

__device__ __forceinline__ uint32_t smem_u32(const void* p) {
    uint32_t a;
    asm("{ .reg .u64 t; cvta.to.shared.u64 t, %1; cvt.u32.u64 %0, t; }" : "=r"(a) : "l"(p));
    return a;
}
__device__ __forceinline__ void cp16(uint32_t dst, const void* src) {
    asm volatile("cp.async.cg.shared.global [%0], [%1], 16;" :: "r"(dst), "l"(src));
}
#define CP_COMMIT() asm volatile("cp.async.commit_group;" ::: "memory")
#define CP_WAIT0()  asm volatile("cp.async.wait_group 0;" ::: "memory")
#define CP_WAIT1()  asm volatile("cp.async.wait_group 1;" ::: "memory")

__device__ __forceinline__ void ldm_x4(uint32_t addr, uint32_t& r0, uint32_t& r1,
                                       uint32_t& r2, uint32_t& r3) {
    asm volatile("ldmatrix.sync.aligned.m8n8.x4.shared.b16 {%0,%1,%2,%3}, [%4];"
                 : "=r"(r0), "=r"(r1), "=r"(r2), "=r"(r3) : "r"(addr));
}
__device__ __forceinline__ void mma_bf16(float* d, const uint32_t* a, const uint32_t* b) {
    asm volatile(
        "mma.sync.aligned.m16n8k16.row.col.f32.bf16.bf16.f32 "
        "{%0,%1,%2,%3}, {%4,%5,%6,%7}, {%8,%9}, {%0,%1,%2,%3};"
        : "+f"(d[0]), "+f"(d[1]), "+f"(d[2]), "+f"(d[3])
        : "r"(a[0]), "r"(a[1]), "r"(a[2]), "r"(a[3]), "r"(b[0]), "r"(b[1]));
}

// =====================================================================
// Kernel 1: VQ quantize (verified)
// =====================================================================
#define VQ_ROWS 16

__global__ __launch_bounds__(512) void vq_kernel(
    const float* __restrict__ weight, const float* __restrict__ embed)
{
    __shared__ float w_s[VQ_ROWS][WDIM];
    __shared__ float wn_s[VQ_ROWS];
    __shared__ float dist_s[VQ_ROWS][NCODE];

    const int tid = threadIdx.x;
    const int r0  = blockIdx.x * VQ_ROWS;

    for (int t = tid; t < VQ_ROWS * WDIM; t += 512)
        w_s[t / WDIM][t % WDIM] = weight[r0 * WDIM + t];
    __syncthreads();

    if (tid < VQ_ROWS) {
        float s = 0.f;
#pragma unroll
        for (int k = 0; k < WDIM; k++) { float v = w_s[tid][k]; s += v * v; }
        wn_s[tid] = s;
    }

    float acc[VQ_ROWS];
#pragma unroll
    for (int r = 0; r < VQ_ROWS; r++) acc[r] = 0.f;
    float en = 0.f;
    const int j = tid;
#pragma unroll 4
    for (int k = 0; k < WDIM; k++) {
        float e = embed[k * NCODE + j];
        en += e * e;
#pragma unroll
        for (int r = 0; r < VQ_ROWS; r++) acc[r] += w_s[r][k] * e;
    }
#pragma unroll
    for (int r = 0; r < VQ_ROWS; r++) dist_s[r][j] = en - 2.f * acc[r];
    __syncthreads();

    const int warp = tid >> 5, lane = tid & 31;
    float best = 3.4e38f; int bi = 0;
    for (int c = lane; c < NCODE; c += 32) {
        float v = dist_s[warp][c];
        if (v < best) { best = v; bi = c; }
    }
#pragma unroll
    for (int off = 16; off > 0; off >>= 1) {
        float ov = __shfl_down_sync(0xffffffffu, best, off);
        int   oi = __shfl_down_sync(0xffffffffu, bi,   off);
        if (ov < best) { best = ov; bi = oi; }
    }
    if (lane == 0) {
        g_idx[r0 + warp]  = bi;
        g_mind[r0 + warp] = wn_s[warp] + best;
    }
}

// =====================================================================
// Kernel 2: x -> A2 bf16 [8192][1024], segments [Ah | Al]
// =====================================================================
__global__ __launch_bounds__(256) void convert_a(const float* __restrict__ x)
{
    const int t = blockIdx.x * 256 + threadIdx.x;
    const int m = t >> 8;
    const int k = (t & 255) * 2;

    const float2 v = *(const float2*)&x[m * NKDIM + k];
    __nv_bfloat162 hi = __float22bfloat162_rn(v);
    float2 res = make_float2(v.x - __bfloat162float(hi.x), v.y - __bfloat162float(hi.y));
    __nv_bfloat162 lo = __float22bfloat162_rn(res);

    __nv_bfloat16* row = g_A2 + (size_t)m * KA;
    *(__nv_bfloat162*)&row[k]       = hi;
    *(__nv_bfloat162*)&row[512 + k] = lo;
}

// =====================================================================
// Kernel 3: W_eff^T -> B2 bf16 [512 n][1024 k], segments [Bh | Bl].
// Block 0 additionally reduces g_mind -> out[B*NOUT] (deterministic).
// =====================================================================
__global__ __launch_bounds__(256) void convert_b(
    const float* __restrict__ embed, const float* __restrict__ weight,
    const int* __restrict__ use_qw_p, float* __restrict__ out, int out_size)
{
    const int n = blockIdx.x;          // 0..511
    const int k = threadIdx.x * 2;     // even k
    const int g = k >> 3, i0 = k & 7;
    const int og = n >> 3, om = n & 7;
    const int uq = use_qw_p ? *use_qw_p : 1;

    float v0, v1;
    if (uq) {
        const int ix = g_idx[g * 64 + og];
        v0 = embed[(i0 * 8 + om) * NCODE + ix];
        v1 = embed[((i0 + 1) * 8 + om) * NCODE + ix];
    } else {
        v0 = weight[(g * 64 + og) * WDIM + i0 * 8 + om];
        v1 = weight[(g * 64 + og) * WDIM + (i0 + 1) * 8 + om];
    }
    __nv_bfloat162 hi = __float22bfloat162_rn(make_float2(v0, v1));
    __nv_bfloat162 lo = __float22bfloat162_rn(
        make_float2(v0 - __bfloat162float(hi.x), v1 - __bfloat162float(hi.y)));

    __nv_bfloat16* row = g_B2 + (size_t)n * KB;
    *(__nv_bfloat162*)&row[k]       = hi;
    *(__nv_bfloat162*)&row[512 + k] = lo;

    // block 0: fold the diff reduction in (saves a dedicated 7us launch)
    if (blockIdx.x == 0) {
        __shared__ float s[256];
        float a = 0.f;
        for (int i = threadIdx.x; i < GROUPS; i += 256) a += g_mind[i];
        s[threadIdx.x] = a;
        __syncthreads();
        for (int st = 128; st > 0; st >>= 1) {
            if (threadIdx.x < st) s[threadIdx.x] += s[threadIdx.x + st];
            __syncthreads();
        }
        if (threadIdx.x == 0 && out_size > BROWS * NOUT)
            out[BROWS * NOUT] = uq ? (s[0] / (float)(GROUPS * WDIM)) : 0.f;
    }
}

// =====================================================================
// Kernel 4: bf16 mma.sync GEMM, 128x128 tile, 8 warps (4m x 2n),
// BK=32, 3-stage cp.async pipeline (dynamic smem), chunk->segment remap:
//   A chunks: [0,16)->Ah, [16,32)->Al, [32,48)->Ah (re-read, L2-hot)
//   B chunks: [0,16)->Bh, [16,32)->Bh, [32,48)->Bl
// =====================================================================
__global__ __launch_bounds__(256, 2) void gemm_mma(float* __restrict__ C)
{
    extern __shared__ __nv_bfloat16 sdyn[];
    __nv_bfloat16* const AsBase = sdyn;                      // [NSTAGE][GBM][ASTR]
    __nv_bfloat16* const BsBase = sdyn + NSTAGE * GBM * ASTR;

    const int tid  = threadIdx.x;
    const int lane = tid & 31;
    const int wid  = tid >> 5;
    const int wm   = wid & 3;
    const int wn   = wid >> 2;

    const int m0 = blockIdx.y * GBM;
    const int n0 = blockIdx.x * GBN;

    const __nv_bfloat16* Ag = g_A2 + (size_t)m0 * KA;
    const __nv_bfloat16* Bg = g_B2 + (size_t)n0 * KB;

    const int c0_row = tid >> 2;
    const int cseg   = tid & 3;
    const int c1_row = c0_row + 64;

    float acc[2][8][4];
#pragma unroll
    for (int mt = 0; mt < 2; mt++)
#pragma unroll
        for (int nt = 0; nt < 8; nt++)
#pragma unroll
            for (int q = 0; q < 4; q++) acc[mt][nt][q] = 0.f;

    auto load_stage = [&](int s, int c) {
        const int ka = (c < 32 ? c : c - 32) * GBK;   // Ah/Al/Ah
        const int kb = (c < 16 ? c : c - 16) * GBK;   // Bh/Bh/Bl
        __nv_bfloat16* As = AsBase + s * (GBM * ASTR);
        __nv_bfloat16* Bs = BsBase + s * (GBN * ASTR);
        cp16(smem_u32(&As[c0_row * ASTR + cseg * 8]), Ag + (size_t)c0_row * KA + ka + cseg * 8);
        cp16(smem_u32(&As[c1_row * ASTR + cseg * 8]), Ag + (size_t)c1_row * KA + ka + cseg * 8);
        cp16(smem_u32(&Bs[c0_row * ASTR + cseg * 8]), Bg + (size_t)c0_row * KB + kb + cseg * 8);
        cp16(smem_u32(&Bs[c1_row * ASTR + cseg * 8]), Bg + (size_t)c1_row * KB + kb + cseg * 8);
    };

    load_stage(0, 0); CP_COMMIT();
    load_stage(1, 1); CP_COMMIT();

    int s = 0;
    for (int it = 0; it < KITERS; it++) {
        if (it >= KITERS - 2) { CP_WAIT0(); } else { CP_WAIT1(); }
        __syncthreads();
        if (it + 2 < KITERS) {
            int sn = s + 2; if (sn >= NSTAGE) sn -= NSTAGE;
            load_stage(sn, it + 2);
            CP_COMMIT();
        }

        const __nv_bfloat16* As = AsBase + s * (GBM * ASTR);
        const __nv_bfloat16* Bs = BsBase + s * (GBN * ASTR);
        const uint32_t a_lane0 = smem_u32(As) +
            ((wm * 32 + (lane & 15)) * ASTR + (lane >> 4) * 8) * 2;
        const int bq = lane >> 3, br = lane & 7;
        const uint32_t b_lane0 = smem_u32(Bs) +
            ((wn * 64 + (bq >> 1) * 8 + br) * ASTR + (bq & 1) * 8) * 2;

#pragma unroll
        for (int ks = 0; ks < 2; ks++) {
            uint32_t a[2][4], b[8][2];
#pragma unroll
            for (int mt = 0; mt < 2; mt++)
                ldm_x4(a_lane0 + (mt * 16 * ASTR + ks * 16) * 2,
                       a[mt][0], a[mt][1], a[mt][2], a[mt][3]);
#pragma unroll
            for (int np = 0; np < 4; np++)
                ldm_x4(b_lane0 + (np * 16 * ASTR + ks * 16) * 2,
                       b[np * 2][0], b[np * 2][1], b[np * 2 + 1][0], b[np * 2 + 1][1]);
#pragma unroll
            for (int mt = 0; mt < 2; mt++)
#pragma unroll
                for (int nt = 0; nt < 8; nt++)
                    mma_bf16(acc[mt][nt], a[mt], b[nt]);
        }

        if (++s >= NSTAGE) s = 0;
    }

    // Epilogue
#pragma unroll
    for (int mt = 0; mt < 2; mt++) {
        const int r0 = m0 + wm * 32 + mt * 16 + (lane >> 2);
#pragma unroll
        for (int nt = 0; nt < 8; nt++) {
            const int c = n0 + wn * 64 + nt * 8 + (lane & 3) * 2;
            *(float2*)&C[(size_t)r0 * NOUT + c]       = make_float2(acc[mt][nt][0], acc[mt][nt][1]);
            *(float2*)&C[(size_t)(r0 + 8) * NOUT + c] = make_float2(acc[mt][nt][2], acc[mt][nt][3]);
        }
    }
}

// =====================================================================
extern "C" void kernel_launch(void* const* d_in, const int* in_sizes, int n_in,
                              void* d_out, int out_size)
{
    const float* x      = (const float*)d_in[0];   // [8192, 512]
    const float* weight = (const float*)d_in[1];   // [64,64,8,8]
    const float* embed  = (const float*)d_in[2];   // [64,512]
    const int*   use_qw = (n_in >= 4) ? (const int*)d_in[3] : nullptr;
    float* out = (float*)d_out;

    cudaFuncSetAttribute(gemm_mma, cudaFuncAttributeMaxDynamicSharedMemorySize,
                         SMEM_ELEMS * (int)sizeof(__nv_bfloat16));

    vq_kernel<<<GROUPS / VQ_ROWS, 512>>>(weight, embed);
    convert_b<<<NOUT, 256>>>(embed, weight, use_qw, out, out_size);
    convert_a<<<BROWS, 256>>>(x);
    gemm_mma<<<dim3(NOUT / GBN, BROWS / GBM), 256,
               SMEM_ELEMS * (int)sizeof(__nv_bfloat16)>>>(out);
}

// round 8
// speedup vs baseline: 1.7101x; 1.7101x over previous
#include <cuda_runtime.h>
#include <cuda_bf16.h>
#include <cstdint>

typedef unsigned long long ull;

#define BROWS 8192
#define NOUT  512
#define NKDIM 512
#define NCODE 512
#define GROUPS 4096
#define WDIM   64

#define KEFF  1536          // 3 precision segments * 512
#define GBM   128
#define GBN   128
#define GBK   32
#define KITERS (KEFF / GBK) // 48
#define ASTR  40            // padded bf16 row stride (80B -> conflict-free ldmatrix)

// ---------------- device scratch ----------------
__device__ __nv_bfloat16 g_A2[BROWS * KEFF];   // 25.2 MB
__device__ __nv_bfloat16 g_B2[NOUT * KEFF];    // 1.6 MB
__device__ int   g_idx[GROUPS];
__device__ float g_mind[GROUPS];

__device__ __forceinline__ uint32_t smem_u32(const void* p) {
    uint32_t a;
    asm("{ .reg .u64 t; cvta.to.shared.u64 t, %1; cvt.u32.u64 %0, t; }" : "=r"(a) : "l"(p));
    return a;
}
__device__ __forceinline__ void cp16(uint32_t dst, const void* src) {
    asm volatile("cp.async.cg.shared.global [%0], [%1], 16;" :: "r"(dst), "l"(src));
}
#define CP_COMMIT() asm volatile("cp.async.commit_group;" ::: "memory")
#define CP_WAIT0()  asm volatile("cp.async.wait_group 0;" ::: "memory")

__device__ __forceinline__ void ldm_x4(uint32_t addr, uint32_t& r0, uint32_t& r1,
                                       uint32_t& r2, uint32_t& r3) {
    asm volatile("ldmatrix.sync.aligned.m8n8.x4.shared.b16 {%0,%1,%2,%3}, [%4];"
                 : "=r"(r0), "=r"(r1), "=r"(r2), "=r"(r3) : "r"(addr));
}
__device__ __forceinline__ void mma_bf16(float* d, const uint32_t* a, const uint32_t* b) {
    asm volatile(
        "mma.sync.aligned.m16n8k16.row.col.f32.bf16.bf16.f32 "
        "{%0,%1,%2,%3}, {%4,%5,%6,%7}, {%8,%9}, {%0,%1,%2,%3};"
        : "+f"(d[0]), "+f"(d[1]), "+f"(d[2]), "+f"(d[3])
        : "r"(a[0]), "r"(a[1]), "r"(a[2]), "r"(a[3]), "r"(b[0]), "r"(b[1]));
}

// =====================================================================
// Kernel 1: VQ quantize (verified R5)
// =====================================================================
#define VQ_ROWS 16

__global__ __launch_bounds__(512) void vq_kernel(
    const float* __restrict__ weight, const float* __restrict__ embed)
{
    __shared__ float w_s[VQ_ROWS][WDIM];
    __shared__ float wn_s[VQ_ROWS];
    __shared__ float dist_s[VQ_ROWS][NCODE];

    const int tid = threadIdx.x;
    const int r0  = blockIdx.x * VQ_ROWS;

    for (int t = tid; t < VQ_ROWS * WDIM; t += 512)
        w_s[t / WDIM][t % WDIM] = weight[r0 * WDIM + t];
    __syncthreads();

    if (tid < VQ_ROWS) {
        float s = 0.f;
#pragma unroll
        for (int k = 0; k < WDIM; k++) { float v = w_s[tid][k]; s += v * v; }
        wn_s[tid] = s;
    }

    float acc[VQ_ROWS];
#pragma unroll
    for (int r = 0; r < VQ_ROWS; r++) acc[r] = 0.f;
    float en = 0.f;
    const int j = tid;
#pragma unroll 4
    for (int k = 0; k < WDIM; k++) {
        float e = embed[k * NCODE + j];
        en += e * e;
#pragma unroll
        for (int r = 0; r < VQ_ROWS; r++) acc[r] += w_s[r][k] * e;
    }
#pragma unroll
    for (int r = 0; r < VQ_ROWS; r++) dist_s[r][j] = en - 2.f * acc[r];
    __syncthreads();

    const int warp = tid >> 5, lane = tid & 31;
    float best = 3.4e38f; int bi = 0;
    for (int c = lane; c < NCODE; c += 32) {
        float v = dist_s[warp][c];
        if (v < best) { best = v; bi = c; }
    }
#pragma unroll
    for (int off = 16; off > 0; off >>= 1) {
        float ov = __shfl_down_sync(0xffffffffu, best, off);
        int   oi = __shfl_down_sync(0xffffffffu, bi,   off);
        if (ov < best) { best = ov; bi = oi; }
    }
    if (lane == 0) {
        g_idx[r0 + warp]  = bi;
        g_mind[r0 + warp] = wn_s[warp] + best;
    }
}

// =====================================================================
// Kernel 2: x -> A2 bf16 row-major [8192][1536], segments [Ah | Al | Ah]
// (verified R5)
// =====================================================================
__global__ __launch_bounds__(256) void convert_a(const float* __restrict__ x)
{
    const int t = blockIdx.x * 256 + threadIdx.x;
    const int m = t >> 8;
    const int k = (t & 255) * 2;

    const float2 v = *(const float2*)&x[m * NKDIM + k];
    __nv_bfloat162 hi = __float22bfloat162_rn(v);
    float2 res = make_float2(v.x - __bfloat162float(hi.x), v.y - __bfloat162float(hi.y));
    __nv_bfloat162 lo = __float22bfloat162_rn(res);

    __nv_bfloat16* row = g_A2 + (size_t)m * KEFF;
    *(__nv_bfloat162*)&row[k]        = hi;
    *(__nv_bfloat162*)&row[512 + k]  = lo;
    *(__nv_bfloat162*)&row[1024 + k] = hi;
}

// =====================================================================
// Kernel 3: W_eff^T -> B2 bf16 [512 n][1536 k], segs [Bh | Bh | Bl].
// Block 0 additionally folds the deterministic diff reduction.
// =====================================================================
__global__ __launch_bounds__(256) void convert_b(
    const float* __restrict__ embed, const float* __restrict__ weight,
    const int* __restrict__ use_qw_p, float* __restrict__ out, int out_size)
{
    const int n = blockIdx.x;          // 0..511
    const int k = threadIdx.x * 2;     // even k
    const int g = k >> 3, i0 = k & 7;
    const int og = n >> 3, om = n & 7;
    const int uq = use_qw_p ? *use_qw_p : 1;

    float v0, v1;
    if (uq) {
        const int ix = g_idx[g * 64 + og];
        v0 = embed[(i0 * 8 + om) * NCODE + ix];
        v1 = embed[((i0 + 1) * 8 + om) * NCODE + ix];
    } else {
        v0 = weight[(g * 64 + og) * WDIM + i0 * 8 + om];
        v1 = weight[(g * 64 + og) * WDIM + (i0 + 1) * 8 + om];
    }
    __nv_bfloat162 hi = __float22bfloat162_rn(make_float2(v0, v1));
    __nv_bfloat162 lo = __float22bfloat162_rn(
        make_float2(v0 - __bfloat162float(hi.x), v1 - __bfloat162float(hi.y)));

    __nv_bfloat16* row = g_B2 + (size_t)n * KEFF;
    *(__nv_bfloat162*)&row[k]        = hi;
    *(__nv_bfloat162*)&row[512 + k]  = hi;
    *(__nv_bfloat162*)&row[1024 + k] = lo;

    if (blockIdx.x == 0) {
        __shared__ float s[256];
        float a = 0.f;
        for (int i = threadIdx.x; i < GROUPS; i += 256) a += g_mind[i];
        s[threadIdx.x] = a;
        __syncthreads();
        for (int st = 128; st > 0; st >>= 1) {
            if (threadIdx.x < st) s[threadIdx.x] += s[threadIdx.x + st];
            __syncthreads();
        }
        if (threadIdx.x == 0 && out_size > BROWS * NOUT)
            out[BROWS * NOUT] = uq ? (s[0] / (float)(GROUPS * WDIM)) : 0.f;
    }
}

// =====================================================================
// Kernel 4: bf16 mma.sync GEMM — byte-identical to verified R5 config.
// 128x128 CTA tile, 8 warps (4m x 2n), BK=32, 2-stage static-smem
// cp.async pipeline.
// =====================================================================
__global__ __launch_bounds__(256, 2) void gemm_mma(float* __restrict__ C)
{
    __shared__ __nv_bfloat16 As[2][GBM][ASTR];  // 20 KB
    __shared__ __nv_bfloat16 Bs[2][GBN][ASTR];  // 20 KB

    const int tid  = threadIdx.x;
    const int lane = tid & 31;
    const int wid  = tid >> 5;
    const int wm   = wid & 3;
    const int wn   = wid >> 2;

    const int m0 = blockIdx.y * GBM;
    const int n0 = blockIdx.x * GBN;

    const __nv_bfloat16* Ag = g_A2 + (size_t)m0 * KEFF;
    const __nv_bfloat16* Bg = g_B2 + (size_t)n0 * KEFF;

    const int c0_row = tid >> 2;
    const int c0_seg = tid & 3;
    const int c1_row = (tid + 256) >> 2;
    const int c1_seg = tid & 3;

    float acc[2][8][4];
#pragma unroll
    for (int mt = 0; mt < 2; mt++)
#pragma unroll
        for (int nt = 0; nt < 8; nt++)
#pragma unroll
            for (int q = 0; q < 4; q++) acc[mt][nt][q] = 0.f;

    auto load_stage = [&](int s, int kt) {
        cp16(smem_u32(&As[s][c0_row][c0_seg * 8]), Ag + (size_t)c0_row * KEFF + kt + c0_seg * 8);
        cp16(smem_u32(&As[s][c1_row][c1_seg * 8]), Ag + (size_t)c1_row * KEFF + kt + c1_seg * 8);
        cp16(smem_u32(&Bs[s][c0_row][c0_seg * 8]), Bg + (size_t)c0_row * KEFF + kt + c0_seg * 8);
        cp16(smem_u32(&Bs[s][c1_row][c1_seg * 8]), Bg + (size_t)c1_row * KEFF + kt + c1_seg * 8);
    };

    load_stage(0, 0);
    CP_COMMIT();

    for (int it = 0; it < KITERS; it++) {
        CP_WAIT0();
        __syncthreads();
        if (it + 1 < KITERS) {
            load_stage((it + 1) & 1, (it + 1) * GBK);
            CP_COMMIT();
        }
        const int s = it & 1;

        const uint32_t a_base = smem_u32(&As[s][0][0]);
        const uint32_t b_base = smem_u32(&Bs[s][0][0]);
        const uint32_t a_lane0 = a_base +
            ((wm * 32 + (lane & 15)) * ASTR + (lane >> 4) * 8) * 2;
        const int bq = lane >> 3, br = lane & 7;
        const uint32_t b_lane0 = b_base +
            ((wn * 64 + (bq >> 1) * 8 + br) * ASTR + (bq & 1) * 8) * 2;

#pragma unroll
        for (int ks = 0; ks < 2; ks++) {
            uint32_t a[2][4], b[8][2];
#pragma unroll
            for (int mt = 0; mt < 2; mt++)
                ldm_x4(a_lane0 + (mt * 16 * ASTR + ks * 16) * 2,
                       a[mt][0], a[mt][1], a[mt][2], a[mt][3]);
#pragma unroll
            for (int np = 0; np < 4; np++)
                ldm_x4(b_lane0 + (np * 16 * ASTR + ks * 16) * 2,
                       b[np * 2][0], b[np * 2][1], b[np * 2 + 1][0], b[np * 2 + 1][1]);
#pragma unroll
            for (int mt = 0; mt < 2; mt++)
#pragma unroll
                for (int nt = 0; nt < 8; nt++)
                    mma_bf16(acc[mt][nt], a[mt], b[nt]);
        }
    }

    // Epilogue
#pragma unroll
    for (int mt = 0; mt < 2; mt++) {
        const int r0 = m0 + wm * 32 + mt * 16 + (lane >> 2);
#pragma unroll
        for (int nt = 0; nt < 8; nt++) {
            const int c = n0 + wn * 64 + nt * 8 + (lane & 3) * 2;
            *(float2*)&C[(size_t)r0 * NOUT + c]       = make_float2(acc[mt][nt][0], acc[mt][nt][1]);
            *(float2*)&C[(size_t)(r0 + 8) * NOUT + c] = make_float2(acc[mt][nt][2], acc[mt][nt][3]);
        }
    }
}

// =====================================================================
extern "C" void kernel_launch(void* const* d_in, const int* in_sizes, int n_in,
                              void* d_out, int out_size)
{
    const float* x      = (const float*)d_in[0];   // [8192, 512]
    const float* weight = (const float*)d_in[1];   // [64,64,8,8]
    const float* embed  = (const float*)d_in[2];   // [64,512]
    const int*   use_qw = (n_in >= 4) ? (const int*)d_in[3] : nullptr;
    float* out = (float*)d_out;

    vq_kernel<<<GROUPS / VQ_ROWS, 512>>>(weight, embed);
    convert_b<<<NOUT, 256>>>(embed, weight, use_qw, out, out_size);
    convert_a<<<BROWS, 256>>>(x);
    gemm_mma<<<dim3(NOUT / GBN, BROWS / GBM), 256>>>(out);
}